// round 2
// baseline (speedup 1.0000x reference)
#include <cuda_runtime.h>

// ---------------------------------------------------------------------------
// Problem constants
//   B=64, S=20, E=512, H=512, V=32000, C=1000
//   D1 = S*E + 2*E = 11264, 4H = 2048
// ---------------------------------------------------------------------------
#define Bsz   64
#define Hdim  512
#define G4H   2048
#define D1dim 11264
#define Vdim  32000

// Scratch (device globals — allocation-free per harness rules)
static __device__ float g_zpart[24 * Bsz * G4H];       // 12.6 MB (up to 23 split slices)
static __device__ float g_hbuf[2][Bsz * Hdim];
static __device__ float g_cbuf[2][Bsz * Hdim];
static __device__ float g_logits[2 * Bsz * Vdim];      // 16.4 MB (2 split-K slices)

// ---------------------------------------------------------------------------
// f32x2 packed helpers (SASS FFMA2 path — 2x fp32 FMA throughput)
// ---------------------------------------------------------------------------
__device__ __forceinline__ unsigned long long pack2(float lo, float hi) {
    unsigned long long r;
    asm("mov.b64 %0, {%1, %2};" : "=l"(r) : "f"(lo), "f"(hi));
    return r;
}
__device__ __forceinline__ void unpack2(unsigned long long v, float& lo, float& hi) {
    asm("mov.b64 {%0, %1}, %2;" : "=f"(lo), "=f"(hi) : "l"(v));
}
__device__ __forceinline__ void fma2(unsigned long long& d, unsigned long long a,
                                     unsigned long long b) {
    asm("fma.rn.f32x2 %0, %1, %2, %0;" : "+l"(d) : "l"(a), "l"(b));
}

__device__ __forceinline__ float sigmoidf_fast(float x) {
    return 1.0f / (1.0f + __expf(-x));
}

// ---------------------------------------------------------------------------
// Split-K partial GEMM:  Zp[sp][m][n] = sum_{k in chunk} X[m][k] * W[k][n]
//   M = 64 (full batch), tile N = 128, BK = 16.
//   Two (X, W) matrix pairs: split indices [0, s1) -> pair 1 (chunk kc1);
//   [s1, gridDim.y) -> pair 2 (chunk kc2).
//   FUSED: pair-1 X is the virtual concat [enc_flat | word | persona[spk]]
//   (width 11264), loaded with a 3-way per-float4 source select.
//   256 threads; per-thread 8 rows x 4 cols held as 16 f32x2 accumulators.
//   X stored PRE-DUPLICATED in smem (each value packed twice) so the inner
//   loop is pure LDS.128 + FFMA2 with no pack MOVs.
// ---------------------------------------------------------------------------
template<bool FUSED>
__global__ __launch_bounds__(256, 2) void gemm_partial_kernel(
    const float* __restrict__ X1, const float* __restrict__ Wm1,
    int ldx1, int s1, int kc1,
    const float* __restrict__ X2, const float* __restrict__ Wm2,
    int ldx2, int kc2,
    int N, float* __restrict__ Zp,
    const float* __restrict__ enc, const float* __restrict__ word,
    const float* __restrict__ persona, const int* __restrict__ speaker)
{
    __shared__ __align__(16) unsigned long long Xd[2][16][64];  // dup-packed X
    __shared__ __align__(16) float Ws[2][16][128];

    const int tid = threadIdx.x;
    const int tx = tid & 31;        // col group: cols tx*4 .. tx*4+3
    const int ty = tid >> 5;        // row group: rows ty*8 .. ty*8+7
    const int n0 = blockIdx.x * 128;
    const int sp = blockIdx.y;

    const bool isP1 = (sp < s1);
    const float* Wm = isP1 ? Wm1 : Wm2;
    const int kc = isP1 ? kc1 : kc2;
    const int k0 = isP1 ? sp * kc1 : (sp - s1) * kc2;

    // X loader mapping: thread -> (row xr, k sub-offset xq)
    const int xr = tid >> 2;            // 0..63
    const int xq = (tid & 3) * 4;       // 0,4,8,12

    const float *encp = nullptr, *wordp = nullptr, *persp = nullptr;
    const float *xbase = nullptr;
    if (FUSED && isP1) {
        int spk = speaker[xr];
        encp  = enc + (long long)xr * 10240;
        wordp = word + (long long)xr * 512 - 10240;
        persp = persona + (long long)spk * 512 - 10752;
    } else {
        const float* X = isP1 ? X1 : X2;
        const int ldx = isP1 ? ldx1 : ldx2;
        xbase = X + (long long)xr * ldx + k0 + xq;
    }

    // W loader mapping
    const int wrow = ty;                // 0..7
    const int wc = tx * 4;
    const float* wbase = Wm + (long long)(k0 + wrow) * N + n0 + wc;

    auto load_x = [&](int t) -> float4 {
        if (FUSED && isP1) {
            int kg = k0 + xq + t * 16;
            const float* p = (kg < 10240) ? (encp + kg)
                           : (kg < 10752) ? (wordp + kg)
                                          : (persp + kg);
            return *reinterpret_cast<const float4*>(p);
        } else {
            return *reinterpret_cast<const float4*>(xbase + t * 16);
        }
    };

    // preload tile 0
    float4 px  = load_x(0);
    float4 pw0 = *reinterpret_cast<const float4*>(wbase);
    float4 pw1 = *reinterpret_cast<const float4*>(wbase + 8LL * N);
    Xd[0][xq + 0][xr] = pack2(px.x, px.x);
    Xd[0][xq + 1][xr] = pack2(px.y, px.y);
    Xd[0][xq + 2][xr] = pack2(px.z, px.z);
    Xd[0][xq + 3][xr] = pack2(px.w, px.w);
    *reinterpret_cast<float4*>(&Ws[0][wrow][wc])     = pw0;
    *reinterpret_cast<float4*>(&Ws[0][wrow + 8][wc]) = pw1;
    __syncthreads();

    unsigned long long acc[8][2];
#pragma unroll
    for (int r = 0; r < 8; r++) { acc[r][0] = 0ULL; acc[r][1] = 0ULL; }

    const int ntiles = kc / 16;
    int buf = 0;
    for (int t = 0; t < ntiles; t++) {
        const bool has_next = (t + 1 < ntiles);
        if (has_next) {
            px = load_x(t + 1);
            const float* wp2 = wbase + (long long)(t + 1) * 16 * N;
            pw0 = *reinterpret_cast<const float4*>(wp2);
            pw1 = *reinterpret_cast<const float4*>(wp2 + 8LL * N);
        }
#pragma unroll
        for (int kk = 0; kk < 16; kk++) {
            ulonglong2 wp = *reinterpret_cast<const ulonglong2*>(&Ws[buf][kk][tx * 4]);
            ulonglong2 x01 = *reinterpret_cast<const ulonglong2*>(&Xd[buf][kk][ty * 8 + 0]);
            ulonglong2 x23 = *reinterpret_cast<const ulonglong2*>(&Xd[buf][kk][ty * 8 + 2]);
            ulonglong2 x45 = *reinterpret_cast<const ulonglong2*>(&Xd[buf][kk][ty * 8 + 4]);
            ulonglong2 x67 = *reinterpret_cast<const ulonglong2*>(&Xd[buf][kk][ty * 8 + 6]);
            fma2(acc[0][0], x01.x, wp.x); fma2(acc[0][1], x01.x, wp.y);
            fma2(acc[1][0], x01.y, wp.x); fma2(acc[1][1], x01.y, wp.y);
            fma2(acc[2][0], x23.x, wp.x); fma2(acc[2][1], x23.x, wp.y);
            fma2(acc[3][0], x23.y, wp.x); fma2(acc[3][1], x23.y, wp.y);
            fma2(acc[4][0], x45.x, wp.x); fma2(acc[4][1], x45.x, wp.y);
            fma2(acc[5][0], x45.y, wp.x); fma2(acc[5][1], x45.y, wp.y);
            fma2(acc[6][0], x67.x, wp.x); fma2(acc[6][1], x67.x, wp.y);
            fma2(acc[7][0], x67.y, wp.x); fma2(acc[7][1], x67.y, wp.y);
        }
        __syncthreads();
        if (has_next) {
            int nb = buf ^ 1;
            Xd[nb][xq + 0][xr] = pack2(px.x, px.x);
            Xd[nb][xq + 1][xr] = pack2(px.y, px.y);
            Xd[nb][xq + 2][xr] = pack2(px.z, px.z);
            Xd[nb][xq + 3][xr] = pack2(px.w, px.w);
            *reinterpret_cast<float4*>(&Ws[nb][wrow][wc])     = pw0;
            *reinterpret_cast<float4*>(&Ws[nb][wrow + 8][wc]) = pw1;
            buf = nb;
            __syncthreads();
        }
    }

    // epilogue: acc[r] -> row (ty*8+r), cols tx*4 .. tx*4+3
    float* zbase = Zp + ((long long)sp * 64 + ty * 8) * N + n0 + tx * 4;
#pragma unroll
    for (int r = 0; r < 8; r++) {
        float c0, c1, c2, c3;
        unpack2(acc[r][0], c0, c1);
        unpack2(acc[r][1], c2, c3);
        *reinterpret_cast<float4*>(zbase + (long long)r * N) =
            make_float4(c0, c1, c2, c3);
    }
}

// ---------------------------------------------------------------------------
// Gate kernel: reduce split-K slices + bias, apply Keras LSTM cell
//   (gate order i,f,g,o; activation=relu, recurrent_activation=sigmoid)
//   Optionally mirrors h,c to a second destination (final-layer -> output).
// ---------------------------------------------------------------------------
__global__ void gates_kernel(const float* __restrict__ Zp, int nsl,
                             const float* __restrict__ bias,
                             const float* __restrict__ c_prev,
                             float* __restrict__ h_new,
                             float* __restrict__ c_new,
                             float* __restrict__ h_out2,
                             float* __restrict__ c_out2)
{
    int idx = blockIdx.x * 256 + threadIdx.x;   // < 64*512
    if (idx >= Bsz * Hdim) return;
    int bt = idx >> 9;
    int j = idx & 511;
    float zi = bias[j], zf = bias[512 + j], zg = bias[1024 + j], zo = bias[1536 + j];
    const float* p = Zp + (long long)bt * G4H + j;
    for (int s = 0; s < nsl; s++) {
        zi += p[0];
        zf += p[512];
        zg += p[1024];
        zo += p[1536];
        p += (long long)Bsz * G4H;
    }
    float cv = sigmoidf_fast(zf) * c_prev[idx] + sigmoidf_fast(zi) * fmaxf(zg, 0.0f);
    float hv = sigmoidf_fast(zo) * fmaxf(cv, 0.0f);
    c_new[idx] = cv;
    h_new[idx] = hv;
    if (h_out2) { h_out2[idx] = hv; c_out2[idx] = cv; }
}

// ---------------------------------------------------------------------------
// Softmax over V=32000 per batch row. Logits come as 2 split-K slices + bias.
// ---------------------------------------------------------------------------
__global__ void softmax_kernel(const float* __restrict__ L,
                               const float* __restrict__ bd,
                               float* __restrict__ out)
{
    const int V = Vdim;
    int b = blockIdx.x;
    int tid = threadIdx.x;
    const float* r0 = L + (long long)b * V;
    const float* r1 = L + (long long)(Bsz + b) * V;

    float m = -1e30f, s = 0.0f;
    for (int v = tid; v < V; v += 256) {
        float val = r0[v] + r1[v] + bd[v];
        float nm = fmaxf(m, val);
        s = s * __expf(m - nm) + __expf(val - nm);
        m = nm;
    }
    __shared__ float sm[256], ss[256];
    sm[tid] = m;
    ss[tid] = s;
    __syncthreads();
    for (int st = 128; st > 0; st >>= 1) {
        if (tid < st) {
            float m2 = sm[tid + st], s2 = ss[tid + st];
            float nm = fmaxf(sm[tid], m2);
            ss[tid] = ss[tid] * __expf(sm[tid] - nm) + s2 * __expf(m2 - nm);
            sm[tid] = nm;
        }
        __syncthreads();
    }
    float M = sm[0];
    float Sinv = 1.0f / ss[0];
    for (int v = tid; v < V; v += 256) {
        float val = r0[v] + r1[v] + bd[v];
        out[(long long)b * V + v] = __expf(val - M) * Sinv;
    }
}

// ---------------------------------------------------------------------------
// kernel_launch
// ---------------------------------------------------------------------------
extern "C" void kernel_launch(void* const* d_in, const int* in_sizes, int n_in,
                              void* d_out, int out_size)
{
    const float* enc     = (const float*)d_in[0];
    const float* word    = (const float*)d_in[1];
    const float* h0      = (const float*)d_in[2];
    const float* c0      = (const float*)d_in[3];
    const float* persona = (const float*)d_in[4];
    const float* W1      = (const float*)d_in[5];
    const float* U1      = (const float*)d_in[6];
    const float* b1      = (const float*)d_in[7];
    const float* W2      = (const float*)d_in[8];
    const float* U2      = (const float*)d_in[9];
    const float* b2      = (const float*)d_in[10];
    const float* W3      = (const float*)d_in[11];
    const float* U3      = (const float*)d_in[12];
    const float* b3      = (const float*)d_in[13];
    const float* W4      = (const float*)d_in[14];
    const float* U4      = (const float*)d_in[15];
    const float* b4      = (const float*)d_in[16];
    const float* Wd      = (const float*)d_in[17];
    const float* bd      = (const float*)d_in[18];
    const int*   speaker = (const int*)d_in[19];
    float* out = (float*)d_out;

    void *pz, *ph, *pc, *pl;
    cudaGetSymbolAddress(&pz, g_zpart);
    cudaGetSymbolAddress(&ph, g_hbuf);
    cudaGetSymbolAddress(&pc, g_cbuf);
    cudaGetSymbolAddress(&pl, g_logits);
    float* zp = (float*)pz;
    float* hb = (float*)ph;
    float* cb = (float*)pc;
    float* lg = (float*)pl;
    float* h1b = hb;               // ping
    float* h2b = hb + Bsz * Hdim;  // pong
    float* c1b = cb;
    float* c2b = cb + Bsz * Hdim;

    // 1) layer 1: z = x@W1 (22 splits of 512, x built in-loader) + h0@U1 (1 split)
    gemm_partial_kernel<true><<<dim3(G4H / 128, 23), 256>>>(
        nullptr, W1, 0, 22, 512,
        h0, U1, Hdim, 512,
        G4H, zp, enc, word, persona, speaker);
    gates_kernel<<<(Bsz * Hdim + 255) / 256, 256>>>(zp, 23, b1, c0, h1b, c1b,
                                                    nullptr, nullptr);

    // 2) layers 2..4: z = h@W (8 splits of 64) + h@U (8 splits of 64)
    gemm_partial_kernel<false><<<dim3(G4H / 128, 16), 256>>>(
        h1b, W2, Hdim, 8, 64, h1b, U2, Hdim, 64, G4H, zp,
        nullptr, nullptr, nullptr, nullptr);
    gates_kernel<<<(Bsz * Hdim + 255) / 256, 256>>>(zp, 16, b2, c1b, h2b, c2b,
                                                    nullptr, nullptr);

    gemm_partial_kernel<false><<<dim3(G4H / 128, 16), 256>>>(
        h2b, W3, Hdim, 8, 64, h2b, U3, Hdim, 64, G4H, zp,
        nullptr, nullptr, nullptr, nullptr);
    gates_kernel<<<(Bsz * Hdim + 255) / 256, 256>>>(zp, 16, b3, c2b, h1b, c1b,
                                                    nullptr, nullptr);

    gemm_partial_kernel<false><<<dim3(G4H / 128, 16), 256>>>(
        h1b, W4, Hdim, 8, 64, h1b, U4, Hdim, 64, G4H, zp,
        nullptr, nullptr, nullptr, nullptr);
    // layer-4 gates also mirrors h4,c4 straight into the output tail
    gates_kernel<<<(Bsz * Hdim + 255) / 256, 256>>>(
        zp, 16, b4, c1b, h2b, c2b,
        out + (long long)Bsz * Vdim,
        out + (long long)Bsz * Vdim + Bsz * Hdim);

    // 3) decoder: logits = h4@Wd, split-K = 2 (slices in g_logits)
    gemm_partial_kernel<false><<<dim3(Vdim / 128, 2), 256>>>(
        h2b, Wd, Hdim, 2, 256,
        h2b, Wd, Hdim, 256,
        Vdim, lg,
        nullptr, nullptr, nullptr, nullptr);

    // 4) softmax -> probs at out[0 : 64*32000)
    softmax_kernel<<<Bsz, 256>>>(lg, bd, out);
}